// round 11
// baseline (speedup 1.0000x reference)
#include <cuda_runtime.h>

#define NVERT 8192
#define GRES 64
#define NVOX (GRES*GRES*GRES)   // 262144
#define NMAX 1048576
#define SCANB 512               // 512 blocks x 512 threads covers NVOX
#define FULLM 0xFFFFFFFFu

// ---------------- scratch (device globals; no allocation) ----------------
__device__ unsigned int g_mm[6];        // sortable-uint min(x,y,z), max(x,y,z)
__device__ int g_hist[NVOX];
__device__ int g_off[NVOX + 1];
__device__ int g_cur[NVOX];
__device__ int g_bsum[SCANB];
__device__ int g_bbase[SCANB];
__device__ int g_vid[NMAX];
__device__ float4 g_pts[NMAX];          // voxel-sorted points {x,y,z,bits(origidx)}
__device__ float4 g_vert[NVERT];        // raw {x, y, z, |v|^2}
__device__ int v_off[NVOX + 1];
__device__ float4 g_vs[NVERT];          // cell-sorted, prescaled {2x,2y,2z,|v|^2}
__device__ unsigned short g_vsidx[NVERT];

// monotone float<->uint mapping (min/max via integer atomics)
__device__ __forceinline__ unsigned f2o(float f) {
    unsigned b = __float_as_uint(f);
    return (b & 0x80000000u) ? ~b : (b | 0x80000000u);
}
__device__ __forceinline__ float o2f(unsigned o) {
    unsigned b = (o & 0x80000000u) ? (o & 0x7FFFFFFFu) : ~o;
    return __uint_as_float(b);
}

// shared helper: per-axis extent guards (must match k_vidhist exactly)
__device__ __forceinline__ void grid_params(float& mnx, float& mny, float& mnz,
                                            float& dx, float& dy, float& dz) {
    mnx = o2f(g_mm[0]); mny = o2f(g_mm[1]); mnz = o2f(g_mm[2]);
    float exx = __fsub_rn(o2f(g_mm[3]), mnx);
    float exy = __fsub_rn(o2f(g_mm[4]), mny);
    float exz = __fsub_rn(o2f(g_mm[5]), mnz);
    dx = exx > 0.f ? exx : 1.f;
    dy = exy > 0.f ? exy : 1.f;
    dz = exz > 0.f ? exz : 1.f;
}

// ---------------- 2. global min/max per coordinate ----------------
__global__ void k_minmax(const float* __restrict__ xyz, int n) {
    float mnx = 3.402823466e38f, mny = mnx, mnz = mnx;
    float mxx = -3.402823466e38f, mxy = mxx, mxz = mxx;
    for (int i = blockIdx.x * blockDim.x + threadIdx.x; i < n;
         i += gridDim.x * blockDim.x) {
        float x = xyz[3 * i], y = xyz[3 * i + 1], z = xyz[3 * i + 2];
        mnx = fminf(mnx, x); mny = fminf(mny, y); mnz = fminf(mnz, z);
        mxx = fmaxf(mxx, x); mxy = fmaxf(mxy, y); mxz = fmaxf(mxz, z);
    }
    for (int o = 16; o; o >>= 1) {
        mnx = fminf(mnx, __shfl_xor_sync(FULLM, mnx, o));
        mny = fminf(mny, __shfl_xor_sync(FULLM, mny, o));
        mnz = fminf(mnz, __shfl_xor_sync(FULLM, mnz, o));
        mxx = fmaxf(mxx, __shfl_xor_sync(FULLM, mxx, o));
        mxy = fmaxf(mxy, __shfl_xor_sync(FULLM, mxy, o));
        mxz = fmaxf(mxz, __shfl_xor_sync(FULLM, mxz, o));
    }
    if ((threadIdx.x & 31) == 0) {
        atomicMin(&g_mm[0], f2o(mnx));
        atomicMin(&g_mm[1], f2o(mny));
        atomicMin(&g_mm[2], f2o(mnz));
        atomicMax(&g_mm[3], f2o(mxx));
        atomicMax(&g_mm[4], f2o(mxy));
        atomicMax(&g_mm[5], f2o(mxz));
    }
}

// ---------------- 3. voxel id + histogram (reciprocal-hoisted division) ----
__global__ void k_vidhist(const float* __restrict__ xyz, int n) {
    float mnx, mny, mnz, dx, dy, dz;
    grid_params(mnx, mny, mnz, dx, dy, dz);
    float rx = __fdiv_rn(1.0f, dx);
    float ry = __fdiv_rn(1.0f, dy);
    float rz = __fdiv_rn(1.0f, dz);
    const float HI = (float)(1.0 - 1e-6);
    for (int i = blockIdx.x * blockDim.x + threadIdx.x; i < n;
         i += gridDim.x * blockDim.x) {
        float ux = __fmul_rn(__fsub_rn(xyz[3 * i],     mnx), rx);
        float uy = __fmul_rn(__fsub_rn(xyz[3 * i + 1], mny), ry);
        float uz = __fmul_rn(__fsub_rn(xyz[3 * i + 2], mnz), rz);
        ux = fminf(fmaxf(ux, 0.f), HI);
        uy = fminf(fmaxf(uy, 0.f), HI);
        uz = fminf(fmaxf(uz, 0.f), HI);
        int vx = (int)floorf(__fmul_rn(ux, (float)GRES));
        int vy = (int)floorf(__fmul_rn(uy, (float)GRES));
        int vz = (int)floorf(__fmul_rn(uz, (float)GRES));
        int vid = (vx * GRES + vy) * GRES + vz;
        g_vid[i] = vid;
        atomicAdd(&g_hist[vid], 1);
    }
}

// ---------------- 4. exclusive scan over NVOX (3 kernels) ------------------
__global__ void k_scan_a(const int* __restrict__ hist) {
    __shared__ int sh[512];
    int i = blockIdx.x * 512 + threadIdx.x;
    sh[threadIdx.x] = hist[i];
    __syncthreads();
    for (int off = 256; off; off >>= 1) {
        if (threadIdx.x < off) sh[threadIdx.x] += sh[threadIdx.x + off];
        __syncthreads();
    }
    if (threadIdx.x == 0) g_bsum[blockIdx.x] = sh[0];
}
__global__ void k_scan_b(int* __restrict__ off, int total) {
    __shared__ int sh[512];
    int v = g_bsum[threadIdx.x];
    sh[threadIdx.x] = v;
    __syncthreads();
    for (int o = 1; o < 512; o <<= 1) {
        int t = (threadIdx.x >= o) ? sh[threadIdx.x - o] : 0;
        __syncthreads();
        sh[threadIdx.x] += t;
        __syncthreads();
    }
    g_bbase[threadIdx.x] = sh[threadIdx.x] - v;
    if (threadIdx.x == 0) off[NVOX] = total;
}
__global__ void k_scan_c(const int* __restrict__ hist, int* __restrict__ off,
                         int* __restrict__ cur) {
    __shared__ int sh[512];
    int i = blockIdx.x * 512 + threadIdx.x;
    int v = hist[i];
    sh[threadIdx.x] = v;
    __syncthreads();
    for (int o = 1; o < 512; o <<= 1) {
        int t = (threadIdx.x >= o) ? sh[threadIdx.x - o] : 0;
        __syncthreads();
        sh[threadIdx.x] += t;
        __syncthreads();
    }
    int excl = sh[threadIdx.x] - v + g_bbase[blockIdx.x];
    off[i] = excl;
    cur[i] = excl;
}

// ---------------- 5. counting-sort scatter: packed point records -----------
__global__ void k_scatter(const float* __restrict__ xyz, int n) {
    for (int i = blockIdx.x * blockDim.x + threadIdx.x; i < n;
         i += gridDim.x * blockDim.x) {
        int v = g_vid[i];
        int pos = atomicAdd(&g_cur[v], 1);
        g_pts[pos] = make_float4(xyz[3 * i], xyz[3 * i + 1], xyz[3 * i + 2],
                                 __int_as_float(i));
    }
}

// ---------------- 6. stable selection of 8192 vertices ---------------------
// sel per f32 jnp.linspace: delta = RN((n-1)/8191); s = floor(RN(q*delta)).
__global__ void k_select(float* __restrict__ out, int n) {
    __shared__ int sb[4096];
    __shared__ int info[3];
    int q = blockIdx.x;
    if (threadIdx.x == 0) {
        float delta = __fdiv_rn((float)(n - 1), (float)(NVERT - 1));
        float fv = __fmul_rn((float)q, delta);
        int s = (int)floorf(fv);
        int lo = 0, hi = NVOX;
        while (hi - lo > 1) {
            int mid = (lo + hi) >> 1;
            if (g_off[mid] <= s) lo = mid; else hi = mid;
        }
        info[0] = g_off[lo];
        info[1] = g_off[lo + 1] - g_off[lo];
        info[2] = s - g_off[lo];
    }
    __syncthreads();
    int base = info[0], m = info[1], r = info[2];

    if (m <= 4096) {
        for (int j = threadIdx.x; j < m; j += blockDim.x)
            sb[j] = __float_as_int(g_pts[base + j].w);
        __syncthreads();
        for (int j = threadIdx.x; j < m; j += blockDim.x) {
            int x = sb[j], c = 0;
            for (int t = 0; t < m; t++) c += (sb[t] < x);
            if (c == r) {
                float4 P = g_pts[base + j];
                out[3 * q] = P.x; out[3 * q + 1] = P.y; out[3 * q + 2] = P.z;
                float vn = __fadd_rn(__fadd_rn(__fmul_rn(P.x, P.x), __fmul_rn(P.y, P.y)),
                                     __fmul_rn(P.z, P.z));
                g_vert[q] = make_float4(P.x, P.y, P.z, vn);
            }
        }
    } else {
        for (int j = threadIdx.x; j < m; j += blockDim.x) {
            int x = __float_as_int(g_pts[base + j].w), c = 0;
            for (int t = 0; t < m; t++)
                c += (__float_as_int(g_pts[base + t].w) < x);
            if (c == r) {
                float4 P = g_pts[base + j];
                out[3 * q] = P.x; out[3 * q + 1] = P.y; out[3 * q + 2] = P.z;
                float vn = __fadd_rn(__fadd_rn(__fmul_rn(P.x, P.x), __fmul_rn(P.y, P.y)),
                                     __fmul_rn(P.z, P.z));
                g_vert[q] = make_float4(P.x, P.y, P.z, vn);
            }
        }
    }
}

// ---------------- 6b. single-block vertex CSR: sort + v_off ---------------
// Replaces hist/scan/scatter for the vertex grid (4 launches -> 1).
// key = cell<<13 | q  (18+13 = 31 bits). Bitonic sort in smem, then write
// g_vs/g_vsidx sorted and fill v_off by per-thread monotonic range walk.
__global__ void k_vsort() {
    __shared__ unsigned sk[NVERT];
    int tid = threadIdx.x;
    float mnx, mny, mnz, dx, dy, dz;
    grid_params(mnx, mny, mnz, dx, dy, dz);
    float ivx = __fdiv_rn((float)GRES, dx);
    float ivy = __fdiv_rn((float)GRES, dy);
    float ivz = __fdiv_rn((float)GRES, dz);

    for (int q = tid; q < NVERT; q += 1024) {
        float4 v = g_vert[q];
        int cx = min(max((int)floorf((v.x - mnx) * ivx), 0), GRES - 1);
        int cy = min(max((int)floorf((v.y - mny) * ivy), 0), GRES - 1);
        int cz = min(max((int)floorf((v.z - mnz) * ivz), 0), GRES - 1);
        unsigned cell = (unsigned)((cx * GRES + cy) * GRES + cz);
        sk[q] = (cell << 13) | (unsigned)q;
    }
    __syncthreads();

    for (int k = 2; k <= NVERT; k <<= 1) {
        for (int j = k >> 1; j; j >>= 1) {
            for (int t = tid; t < NVERT; t += 1024) {
                int l = t ^ j;
                if (l > t) {
                    unsigned a = sk[t], b = sk[l];
                    bool up = ((t & k) == 0);
                    if ((a > b) == up) { sk[t] = b; sk[l] = a; }
                }
            }
            __syncthreads();
        }
    }

    for (int s = tid; s < NVERT; s += 1024) {
        int q = (int)(sk[s] & 8191u);
        float4 v = g_vert[q];
        g_vs[s] = make_float4(2.0f * v.x, 2.0f * v.y, 2.0f * v.z, v.w);
        g_vsidx[s] = (unsigned short)q;
    }

    // v_off[c] = #verts with cell < c, for c in [0, NVOX]
    int per = (NVOX + 1 + 1023) / 1024;     // 257
    int c0 = tid * per;
    int c1 = min(c0 + per, NVOX + 1);
    if (c0 < c1) {
        int lo = 0, hi = NVERT;
        while (lo < hi) {
            int mid = (lo + hi) >> 1;
            if ((int)(sk[mid] >> 13) < c0) lo = mid + 1; else hi = mid;
        }
        int j = lo;
        for (int c = c0; c < c1; c++) {
            while (j < NVERT && (int)(sk[j] >> 13) < c) j++;
            v_off[c] = j;
        }
    }
}

// exact reference-formula eval + lexicographic (d, oi) min update
#define EVAL_EXACT(J)                                                          \
    do {                                                                       \
        float4 V = sv[J];                                                      \
        float t2 = fmaf(pz, V.z, fmaf(py, V.y, __fmul_rn(px, V.x)));           \
        float d = __fsub_rn(V.w, t2);                                          \
        int oi = sidx[J];                                                      \
        if (d < bd || (d == bd && oi < bi)) { bd = d; bi = oi; }               \
    } while (0)

// uniform flattened-row box scan with 1-ahead row prefetch (bounds uniform)
#define SCAN_BOX(X0, X1, Y0, Y1, Z0, Z1)                                       \
    do {                                                                       \
        int ny_ = (Y1) - (Y0) + 1;                                             \
        int nr_ = ((X1) - (X0) + 1) * ny_;                                     \
        int ix_ = (X0), iy_ = (Y0);                                            \
        int rb_ = (ix_ * GRES + iy_) * GRES;                                   \
        int sC_ = v_off[rb_ + (Z0)], eC_ = v_off[rb_ + (Z1) + 1];              \
        for (int r_ = 0; r_ < nr_; r_++) {                                     \
            int nix_ = ix_, niy_ = iy_ + 1;                                    \
            if (niy_ > (Y1)) { niy_ = (Y0); nix_ = ix_ + 1; }                  \
            int sN_ = 0, eN_ = 0;                                              \
            if (r_ + 1 < nr_) {                                                \
                int nb_ = (nix_ * GRES + niy_) * GRES;                         \
                sN_ = v_off[nb_ + (Z0)];                                       \
                eN_ = v_off[nb_ + (Z1) + 1];                                   \
            }                                                                  \
            _Pragma("unroll 1")                                                \
            for (int j = sC_; j < eC_; j++) EVAL_EXACT(j);                     \
            sC_ = sN_; eC_ = eN_; ix_ = nix_; iy_ = niy_;                      \
        }                                                                      \
    } while (0)

// ---------------- 7. warp-uniform grid-pruned 1-NN -------------------------
// Lanes are spatially adjacent (voxel-sorted points). All scan boxes are
// UNIONED across the warp so control flow and v_off loads are uniform;
// each lane evaluates with the exact reference formula. Every lane's
// sphere box is a subset of the union -> per-lane coverage guaranteed;
// extra vertices are >=1e-3 (sq) farther, cannot tie-or-beat under float.
__global__ void __launch_bounds__(1024, 1)
k_knn(float* __restrict__ out, int n) {
    extern __shared__ char smem[];
    float4* sv = (float4*)smem;                         // 8192 * 16B
    unsigned short* sidx = (unsigned short*)(smem + NVERT * sizeof(float4));
    for (int j = threadIdx.x; j < NVERT; j += blockDim.x) {
        sv[j] = g_vs[j];
        sidx[j] = g_vsidx[j];
    }
    __syncthreads();

    float mnx, mny, mnz, dx, dy, dz;
    grid_params(mnx, mny, mnz, dx, dy, dz);
    float ivx = __fdiv_rn((float)GRES, dx);
    float ivy = __fdiv_rn((float)GRES, dy);
    float ivz = __fdiv_rn((float)GRES, dz);
    float* pout = out + 3 * NVERT;
    int stride = gridDim.x * blockDim.x;
    int lane = threadIdx.x & 31;

    for (int ib = blockIdx.x * blockDim.x + (threadIdx.x & ~31); ib < n;
         ib += stride) {
        int i = min(ib + lane, n - 1);       // clamped lanes write identical value
        float4 P = g_pts[i];
        float px = P.x, py = P.y, pz = P.z;
        int p = __float_as_int(P.w);
        float fx = (px - mnx) * ivx, fy = (py - mny) * ivy, fz = (pz - mnz) * ivz;
        int cx = min(max((int)floorf(fx), 0), GRES - 1);
        int cy = min(max((int)floorf(fy), 0), GRES - 1);
        int cz = min(max((int)floorf(fz), 0), GRES - 1);
        float pn = fmaf(pz, pz, fmaf(py, py, px * px));

        // per-lane octant 2^3 box
        int ox0 = (fx - (float)cx > 0.5f) ? cx : cx - 1;
        int oy0 = (fy - (float)cy > 0.5f) ? cy : cy - 1;
        int oz0 = (fz - (float)cz > 0.5f) ? cz : cz - 1;
        ox0 = max(ox0, 0); int ox1 = min(ox0 + 1, GRES - 1);
        oy0 = max(oy0, 0); int oy1 = min(oy0 + 1, GRES - 1);
        oz0 = max(oz0, 0); int oz1 = min(oz0 + 1, GRES - 1);

        // warp union box
        int ux0 = __reduce_min_sync(FULLM, ox0);
        int ux1 = __reduce_max_sync(FULLM, ox1);
        int uy0 = __reduce_min_sync(FULLM, oy0);
        int uy1 = __reduce_max_sync(FULLM, oy1);
        int uz0 = __reduce_min_sync(FULLM, oz0);
        int uz1 = __reduce_max_sync(FULLM, oz1);

        float bd = 3.402823466e38f;
        int bi = 0x7FFFFFFF;

        // phase A: scan union box; expand uniformly while empty (rare)
        for (;;) {
            SCAN_BOX(ux0, ux1, uy0, uy1, uz0, uz1);
            if (__all_sync(FULLM, bi != 0x7FFFFFFF)) break;
            if (ux0 == 0 && uy0 == 0 && uz0 == 0 && ux1 == GRES - 1 &&
                uy1 == GRES - 1 && uz1 == GRES - 1) break;
            ux0 = max(ux0 - 1, 0); ux1 = min(ux1 + 1, GRES - 1);
            uy0 = max(uy0 - 1, 0); uy1 = min(uy1 + 1, GRES - 1);
            uz0 = max(uz0 - 1, 0); uz1 = min(uz1 + 1, GRES - 1);
        }

        // phase B: per-lane sphere box -> warp union; uniform containment
        float R = sqrtf(fmaxf(bd + pn, 0.0f) + 1e-3f) + 1e-3f;
        int x0 = min(max((int)floorf((px - R - mnx) * ivx), 0), GRES - 1);
        int x1 = min(max((int)floorf((px + R - mnx) * ivx), 0), GRES - 1);
        int y0 = min(max((int)floorf((py - R - mny) * ivy), 0), GRES - 1);
        int y1 = min(max((int)floorf((py + R - mny) * ivy), 0), GRES - 1);
        int z0 = min(max((int)floorf((pz - R - mnz) * ivz), 0), GRES - 1);
        int z1 = min(max((int)floorf((pz + R - mnz) * ivz), 0), GRES - 1);
        int sx0 = __reduce_min_sync(FULLM, x0);
        int sx1 = __reduce_max_sync(FULLM, x1);
        int sy0 = __reduce_min_sync(FULLM, y0);
        int sy1 = __reduce_max_sync(FULLM, y1);
        int sz0 = __reduce_min_sync(FULLM, z0);
        int sz1 = __reduce_max_sync(FULLM, z1);

        if (sx0 < ux0 || sx1 > ux1 || sy0 < uy0 || sy1 > uy1 ||
            sz0 < uz0 || sz1 > uz1) {
            SCAN_BOX(sx0, sx1, sy0, sy1, sz0, sz1);  // idempotent rescan
        }
        pout[p] = (float)bi;
    }
}

// ---------------- launch ----------------
extern "C" void kernel_launch(void* const* d_in, const int* in_sizes, int n_in,
                              void* d_out, int out_size) {
    const float* xyz = (const float*)d_in[0];
    int n = in_sizes[0] / 3;
    float* out = (float*)d_out;

    int* d_ghist; cudaGetSymbolAddress((void**)&d_ghist, g_hist);
    int* d_goff;  cudaGetSymbolAddress((void**)&d_goff,  g_off);
    int* d_gcur;  cudaGetSymbolAddress((void**)&d_gcur,  g_cur);
    unsigned int* d_mm; cudaGetSymbolAddress((void**)&d_mm, g_mm);

    cudaMemsetAsync(d_ghist, 0, NVOX * sizeof(int));
    cudaMemsetAsync(d_mm, 0xFF, 3 * sizeof(unsigned int));
    cudaMemsetAsync(d_mm + 3, 0x00, 3 * sizeof(unsigned int));

    k_minmax<<<148, 256>>>(xyz, n);
    k_vidhist<<<1024, 256>>>(xyz, n);
    k_scan_a<<<SCANB, 512>>>(d_ghist);
    k_scan_b<<<1, 512>>>(d_goff, n);
    k_scan_c<<<SCANB, 512>>>(d_ghist, d_goff, d_gcur);
    k_scatter<<<1024, 256>>>(xyz, n);
    k_select<<<NVERT, 128>>>(out, n);
    k_vsort<<<1, 1024>>>();

    int smem = NVERT * (int)sizeof(float4) + NVERT * (int)sizeof(unsigned short);
    cudaFuncSetAttribute(k_knn, cudaFuncAttributeMaxDynamicSharedMemorySize, smem);
    k_knn<<<148, 1024, smem>>>(out, n);
}

// round 12
// speedup vs baseline: 1.7613x; 1.7613x over previous
#include <cuda_runtime.h>

#define NVERT 8192
#define GRES 64
#define NVOX (GRES*GRES*GRES)   // 262144
#define NMAX 1048576
#define SCANB 512               // 512 blocks x 512 threads covers NVOX
#define FULLM 0xFFFFFFFFu

// ---------------- scratch (device globals; no allocation) ----------------
__device__ unsigned int g_mm[6];        // sortable-uint min(x,y,z), max(x,y,z)
__device__ int g_hist[NVOX];
__device__ int g_off[NVOX + 1];
__device__ int g_cur[NVOX];
__device__ int g_bsum[SCANB];
__device__ int g_bbase[SCANB];
__device__ float4 g_pts[NMAX];          // voxel-sorted points {x,y,z,bits(origidx)}
__device__ float4 g_vert[NVERT];        // raw {x, y, z, |v|^2}
__device__ int v_off[NVOX + 1];
__device__ float4 g_vs[NVERT];          // cell-sorted, prescaled {2x,2y,2z,|v|^2}
__device__ unsigned short g_vsidx[NVERT];

// monotone float<->uint mapping (min/max via integer atomics)
__device__ __forceinline__ unsigned f2o(float f) {
    unsigned b = __float_as_uint(f);
    return (b & 0x80000000u) ? ~b : (b | 0x80000000u);
}
__device__ __forceinline__ float o2f(unsigned o) {
    unsigned b = (o & 0x80000000u) ? (o & 0x7FFFFFFFu) : ~o;
    return __uint_as_float(b);
}

// shared helper: per-axis extent guards (must match k_vidhist exactly)
__device__ __forceinline__ void grid_params(float& mnx, float& mny, float& mnz,
                                            float& dx, float& dy, float& dz) {
    mnx = o2f(g_mm[0]); mny = o2f(g_mm[1]); mnz = o2f(g_mm[2]);
    float exx = __fsub_rn(o2f(g_mm[3]), mnx);
    float exy = __fsub_rn(o2f(g_mm[4]), mny);
    float exz = __fsub_rn(o2f(g_mm[5]), mnz);
    dx = exx > 0.f ? exx : 1.f;
    dy = exy > 0.f ? exy : 1.f;
    dz = exz > 0.f ? exz : 1.f;
}

// exact voxel id of point (x,y,z) — reference rounding chain
__device__ __forceinline__ int voxel_id(float x, float y, float z,
                                        float mnx, float mny, float mnz,
                                        float rx, float ry, float rz) {
    const float HI = (float)(1.0 - 1e-6);
    float ux = __fmul_rn(__fsub_rn(x, mnx), rx);
    float uy = __fmul_rn(__fsub_rn(y, mny), ry);
    float uz = __fmul_rn(__fsub_rn(z, mnz), rz);
    ux = fminf(fmaxf(ux, 0.f), HI);
    uy = fminf(fmaxf(uy, 0.f), HI);
    uz = fminf(fmaxf(uz, 0.f), HI);
    int vx = (int)floorf(__fmul_rn(ux, (float)GRES));
    int vy = (int)floorf(__fmul_rn(uy, (float)GRES));
    int vz = (int)floorf(__fmul_rn(uz, (float)GRES));
    return (vx * GRES + vy) * GRES + vz;
}

// ---------------- 2. global min/max per coordinate ----------------
__global__ void k_minmax(const float* __restrict__ xyz, int n) {
    float mnx = 3.402823466e38f, mny = mnx, mnz = mnx;
    float mxx = -3.402823466e38f, mxy = mxx, mxz = mxx;
    for (int i = blockIdx.x * blockDim.x + threadIdx.x; i < n;
         i += gridDim.x * blockDim.x) {
        float x = xyz[3 * i], y = xyz[3 * i + 1], z = xyz[3 * i + 2];
        mnx = fminf(mnx, x); mny = fminf(mny, y); mnz = fminf(mnz, z);
        mxx = fmaxf(mxx, x); mxy = fmaxf(mxy, y); mxz = fmaxf(mxz, z);
    }
    for (int o = 16; o; o >>= 1) {
        mnx = fminf(mnx, __shfl_xor_sync(FULLM, mnx, o));
        mny = fminf(mny, __shfl_xor_sync(FULLM, mny, o));
        mnz = fminf(mnz, __shfl_xor_sync(FULLM, mnz, o));
        mxx = fmaxf(mxx, __shfl_xor_sync(FULLM, mxx, o));
        mxy = fmaxf(mxy, __shfl_xor_sync(FULLM, mxy, o));
        mxz = fmaxf(mxz, __shfl_xor_sync(FULLM, mxz, o));
    }
    if ((threadIdx.x & 31) == 0) {
        atomicMin(&g_mm[0], f2o(mnx));
        atomicMin(&g_mm[1], f2o(mny));
        atomicMin(&g_mm[2], f2o(mnz));
        atomicMax(&g_mm[3], f2o(mxx));
        atomicMax(&g_mm[4], f2o(mxy));
        atomicMax(&g_mm[5], f2o(mxz));
    }
}

// ---------------- 3. voxel id + histogram ----------------------------------
__global__ void k_vidhist(const float* __restrict__ xyz, int n) {
    float mnx, mny, mnz, dx, dy, dz;
    grid_params(mnx, mny, mnz, dx, dy, dz);
    float rx = __fdiv_rn(1.0f, dx);
    float ry = __fdiv_rn(1.0f, dy);
    float rz = __fdiv_rn(1.0f, dz);
    for (int i = blockIdx.x * blockDim.x + threadIdx.x; i < n;
         i += gridDim.x * blockDim.x) {
        int vid = voxel_id(xyz[3 * i], xyz[3 * i + 1], xyz[3 * i + 2],
                           mnx, mny, mnz, rx, ry, rz);
        atomicAdd(&g_hist[vid], 1);
    }
}

// ---------------- 4. exclusive scan over NVOX (3 kernels) ------------------
__global__ void k_scan_a(const int* __restrict__ hist) {
    __shared__ int sh[512];
    int i = blockIdx.x * 512 + threadIdx.x;
    sh[threadIdx.x] = hist[i];
    __syncthreads();
    for (int off = 256; off; off >>= 1) {
        if (threadIdx.x < off) sh[threadIdx.x] += sh[threadIdx.x + off];
        __syncthreads();
    }
    if (threadIdx.x == 0) g_bsum[blockIdx.x] = sh[0];
}
__global__ void k_scan_b(int* __restrict__ off, int total) {
    __shared__ int sh[512];
    int v = g_bsum[threadIdx.x];
    sh[threadIdx.x] = v;
    __syncthreads();
    for (int o = 1; o < 512; o <<= 1) {
        int t = (threadIdx.x >= o) ? sh[threadIdx.x - o] : 0;
        __syncthreads();
        sh[threadIdx.x] += t;
        __syncthreads();
    }
    g_bbase[threadIdx.x] = sh[threadIdx.x] - v;
    if (threadIdx.x == 0) off[NVOX] = total;
}
__global__ void k_scan_c(const int* __restrict__ hist, int* __restrict__ off,
                         int* __restrict__ cur) {
    __shared__ int sh[512];
    int i = blockIdx.x * 512 + threadIdx.x;
    int v = hist[i];
    sh[threadIdx.x] = v;
    __syncthreads();
    for (int o = 1; o < 512; o <<= 1) {
        int t = (threadIdx.x >= o) ? sh[threadIdx.x - o] : 0;
        __syncthreads();
        sh[threadIdx.x] += t;
        __syncthreads();
    }
    int excl = sh[threadIdx.x] - v + g_bbase[blockIdx.x];
    off[i] = excl;
    cur[i] = excl;
}

// ---------------- 5. counting-sort scatter: packed point records -----------
__global__ void k_scatter(const float* __restrict__ xyz, int n) {
    float mnx, mny, mnz, dx, dy, dz;
    grid_params(mnx, mny, mnz, dx, dy, dz);
    float rx = __fdiv_rn(1.0f, dx);
    float ry = __fdiv_rn(1.0f, dy);
    float rz = __fdiv_rn(1.0f, dz);
    for (int i = blockIdx.x * blockDim.x + threadIdx.x; i < n;
         i += gridDim.x * blockDim.x) {
        float x = xyz[3 * i], y = xyz[3 * i + 1], z = xyz[3 * i + 2];
        int vid = voxel_id(x, y, z, mnx, mny, mnz, rx, ry, rz);
        int pos = atomicAdd(&g_cur[vid], 1);
        g_pts[pos] = make_float4(x, y, z, __int_as_float(i));
    }
}

// ---------------- 6. stable selection of 8192 vertices ---------------------
// sel per f32 jnp.linspace: delta = RN((n-1)/8191); s = floor(RN(q*delta)).
__global__ void k_select(float* __restrict__ out, int n) {
    __shared__ int sb[4096];
    __shared__ int info[3];
    int q = blockIdx.x;
    if (threadIdx.x == 0) {
        float delta = __fdiv_rn((float)(n - 1), (float)(NVERT - 1));
        float fv = __fmul_rn((float)q, delta);
        int s = (int)floorf(fv);
        int lo = 0, hi = NVOX;
        while (hi - lo > 1) {
            int mid = (lo + hi) >> 1;
            if (g_off[mid] <= s) lo = mid; else hi = mid;
        }
        info[0] = g_off[lo];
        info[1] = g_off[lo + 1] - g_off[lo];
        info[2] = s - g_off[lo];
    }
    __syncthreads();
    int base = info[0], m = info[1], r = info[2];

    if (m <= 4096) {
        for (int j = threadIdx.x; j < m; j += blockDim.x)
            sb[j] = __float_as_int(g_pts[base + j].w);
        __syncthreads();
        for (int j = threadIdx.x; j < m; j += blockDim.x) {
            int x = sb[j], c = 0;
            for (int t = 0; t < m; t++) c += (sb[t] < x);
            if (c == r) {
                float4 P = g_pts[base + j];
                out[3 * q] = P.x; out[3 * q + 1] = P.y; out[3 * q + 2] = P.z;
                float vn = __fadd_rn(__fadd_rn(__fmul_rn(P.x, P.x), __fmul_rn(P.y, P.y)),
                                     __fmul_rn(P.z, P.z));
                g_vert[q] = make_float4(P.x, P.y, P.z, vn);
            }
        }
    } else {
        for (int j = threadIdx.x; j < m; j += blockDim.x) {
            int x = __float_as_int(g_pts[base + j].w), c = 0;
            for (int t = 0; t < m; t++)
                c += (__float_as_int(g_pts[base + t].w) < x);
            if (c == r) {
                float4 P = g_pts[base + j];
                out[3 * q] = P.x; out[3 * q + 1] = P.y; out[3 * q + 2] = P.z;
                float vn = __fadd_rn(__fadd_rn(__fmul_rn(P.x, P.x), __fmul_rn(P.y, P.y)),
                                     __fmul_rn(P.z, P.z));
                g_vert[q] = make_float4(P.x, P.y, P.z, vn);
            }
        }
    }
}

// ---------------- 6b. single-block vertex CSR: sort + v_off ---------------
// key = cell<<13 | q. Bitonic sort in smem, then write g_vs/g_vsidx sorted
// and fill v_off by per-thread monotonic range walk. (Validated in R11.)
__global__ void k_vsort() {
    __shared__ unsigned sk[NVERT];
    int tid = threadIdx.x;
    float mnx, mny, mnz, dx, dy, dz;
    grid_params(mnx, mny, mnz, dx, dy, dz);
    float ivx = __fdiv_rn((float)GRES, dx);
    float ivy = __fdiv_rn((float)GRES, dy);
    float ivz = __fdiv_rn((float)GRES, dz);

    for (int q = tid; q < NVERT; q += 1024) {
        float4 v = g_vert[q];
        int cx = min(max((int)floorf((v.x - mnx) * ivx), 0), GRES - 1);
        int cy = min(max((int)floorf((v.y - mny) * ivy), 0), GRES - 1);
        int cz = min(max((int)floorf((v.z - mnz) * ivz), 0), GRES - 1);
        unsigned cell = (unsigned)((cx * GRES + cy) * GRES + cz);
        sk[q] = (cell << 13) | (unsigned)q;
    }
    __syncthreads();

    for (int k = 2; k <= NVERT; k <<= 1) {
        for (int j = k >> 1; j; j >>= 1) {
            for (int t = tid; t < NVERT; t += 1024) {
                int l = t ^ j;
                if (l > t) {
                    unsigned a = sk[t], b = sk[l];
                    bool up = ((t & k) == 0);
                    if ((a > b) == up) { sk[t] = b; sk[l] = a; }
                }
            }
            __syncthreads();
        }
    }

    for (int s = tid; s < NVERT; s += 1024) {
        int q = (int)(sk[s] & 8191u);
        float4 v = g_vert[q];
        g_vs[s] = make_float4(2.0f * v.x, 2.0f * v.y, 2.0f * v.z, v.w);
        g_vsidx[s] = (unsigned short)q;
    }

    int per = (NVOX + 1 + 1023) / 1024;     // 257
    int c0 = tid * per;
    int c1 = min(c0 + per, NVOX + 1);
    if (c0 < c1) {
        int lo = 0, hi = NVERT;
        while (lo < hi) {
            int mid = (lo + hi) >> 1;
            if ((int)(sk[mid] >> 13) < c0) lo = mid + 1; else hi = mid;
        }
        int j = lo;
        for (int c = c0; c < c1; c++) {
            while (j < NVERT && (int)(sk[j] >> 13) < c) j++;
            v_off[c] = j;
        }
    }
}

// ---------------- 7. grid-pruned 1-NN (R9 structure, best measured) --------
// Phase A: octant 2^3 box, all 8 v_off LDGs issued up-front (MLP=8).
// Phase B: exact reference-formula rescan of sphere box (margin
// sqrt(D+1e-3)+1e-3), flattened rows with 1-ahead (s,e) prefetch.
__global__ void __launch_bounds__(1024, 1)
k_knn(float* __restrict__ out, int n) {
    extern __shared__ char smem[];
    float4* sv = (float4*)smem;                         // 8192 * 16B
    unsigned short* sidx = (unsigned short*)(smem + NVERT * sizeof(float4));
    for (int j = threadIdx.x; j < NVERT; j += blockDim.x) {
        sv[j] = g_vs[j];
        sidx[j] = g_vsidx[j];
    }
    __syncthreads();

    float mnx, mny, mnz, dx, dy, dz;
    grid_params(mnx, mny, mnz, dx, dy, dz);
    float ivx = __fdiv_rn((float)GRES, dx);
    float ivy = __fdiv_rn((float)GRES, dy);
    float ivz = __fdiv_rn((float)GRES, dz);
    float* pout = out + 3 * NVERT;

    for (int i = blockIdx.x * blockDim.x + threadIdx.x; i < n;
         i += gridDim.x * blockDim.x) {
        float4 P = g_pts[i];                // coalesced stream
        float px = P.x, py = P.y, pz = P.z;
        int p = __float_as_int(P.w);
        float fx = (px - mnx) * ivx, fy = (py - mny) * ivy, fz = (pz - mnz) * ivz;
        int cx = min(max((int)floorf(fx), 0), GRES - 1);
        int cy = min(max((int)floorf(fy), 0), GRES - 1);
        int cz = min(max((int)floorf(fz), 0), GRES - 1);

        // ---- phase A: octant 2^3 box, bounds prefetched with MLP=8 ----
        float bestD = 3.402823466e38f;
        {
            int x0 = (fx - (float)cx > 0.5f) ? cx : cx - 1;
            int y0 = (fy - (float)cy > 0.5f) ? cy : cy - 1;
            int z0 = (fz - (float)cz > 0.5f) ? cz : cz - 1;
            x0 = max(x0, 0); int x1 = min(x0 + 1, GRES - 1); x0 = min(x0, x1);
            y0 = max(y0, 0); int y1 = min(y0 + 1, GRES - 1); y0 = min(y0, y1);
            z0 = max(z0, 0); int z1 = min(z0 + 1, GRES - 1); z0 = min(z0, z1);
            int r00 = (x0 * GRES + y0) * GRES;
            int r01 = (x0 * GRES + y1) * GRES;
            int r10 = (x1 * GRES + y0) * GRES;
            int r11 = (x1 * GRES + y1) * GRES;
            int s00 = v_off[r00 + z0], e00 = v_off[r00 + z1 + 1];
            int s01 = v_off[r01 + z0], e01 = v_off[r01 + z1 + 1];
            int s10 = v_off[r10 + z0], e10 = v_off[r10 + z1 + 1];
            int s11 = v_off[r11 + z0], e11 = v_off[r11 + z1 + 1];
            #pragma unroll 1
            for (int j = s00; j < e00; j++) {
                float4 V = sv[j];
                float ddx = px - 0.5f * V.x, ddy = py - 0.5f * V.y, ddz = pz - 0.5f * V.z;
                bestD = fminf(bestD, fmaf(ddz, ddz, fmaf(ddy, ddy, ddx * ddx)));
            }
            #pragma unroll 1
            for (int j = s01; j < e01; j++) {
                float4 V = sv[j];
                float ddx = px - 0.5f * V.x, ddy = py - 0.5f * V.y, ddz = pz - 0.5f * V.z;
                bestD = fminf(bestD, fmaf(ddz, ddz, fmaf(ddy, ddy, ddx * ddx)));
            }
            #pragma unroll 1
            for (int j = s10; j < e10; j++) {
                float4 V = sv[j];
                float ddx = px - 0.5f * V.x, ddy = py - 0.5f * V.y, ddz = pz - 0.5f * V.z;
                bestD = fminf(bestD, fmaf(ddz, ddz, fmaf(ddy, ddy, ddx * ddx)));
            }
            #pragma unroll 1
            for (int j = s11; j < e11; j++) {
                float4 V = sv[j];
                float ddx = px - 0.5f * V.x, ddy = py - 0.5f * V.y, ddz = pz - 0.5f * V.z;
                bestD = fminf(bestD, fmaf(ddz, ddz, fmaf(ddy, ddy, ddx * ddx)));
            }
        }
        // fallback: expanding boxes until any vertex found (rare)
        if (bestD >= 3.0e38f) {
            for (int w = 1; w < GRES; w++) {
                int x0 = max(cx - w, 0), x1 = min(cx + w, GRES - 1);
                int y0 = max(cy - w, 0), y1 = min(cy + w, GRES - 1);
                int z0 = max(cz - w, 0), z1 = min(cz + w, GRES - 1);
                for (int ix = x0; ix <= x1; ix++)
                    for (int iy = y0; iy <= y1; iy++) {
                        int row = (ix * GRES + iy) * GRES;
                        int s = v_off[row + z0];
                        int e = v_off[row + z1 + 1];
                        for (int j = s; j < e; j++) {
                            float4 V = sv[j];
                            float ddx = px - 0.5f * V.x, ddy = py - 0.5f * V.y, ddz = pz - 0.5f * V.z;
                            bestD = fminf(bestD, fmaf(ddz, ddz, fmaf(ddy, ddy, ddx * ddx)));
                        }
                    }
                if (bestD < 3.0e38f) break;
            }
        }

        // ---- phase B: exact rescan of sphere box, 1-ahead row prefetch ----
        float R = sqrtf(bestD + 1e-3f) + 1e-3f;
        int x0 = min(max((int)floorf((px - R - mnx) * ivx), 0), GRES - 1);
        int x1 = min(max((int)floorf((px + R - mnx) * ivx), 0), GRES - 1);
        int y0 = min(max((int)floorf((py - R - mny) * ivy), 0), GRES - 1);
        int y1 = min(max((int)floorf((py + R - mny) * ivy), 0), GRES - 1);
        int z0 = min(max((int)floorf((pz - R - mnz) * ivz), 0), GRES - 1);
        int z1 = min(max((int)floorf((pz + R - mnz) * ivz), 0), GRES - 1);

        float bd = 3.402823466e38f;
        int bi = 0x7FFFFFFF;
        int ny = y1 - y0 + 1;
        int nr = (x1 - x0 + 1) * ny;
        int ix = x0, iy = y0;
        int rowb = (ix * GRES + iy) * GRES;
        int sC = v_off[rowb + z0], eC = v_off[rowb + z1 + 1];
        for (int r = 0; r < nr; r++) {
            int nix = ix, niy = iy + 1;
            if (niy > y1) { niy = y0; nix = ix + 1; }
            int sN = 0, eN = 0;
            if (r + 1 < nr) {
                int nb = (nix * GRES + niy) * GRES;
                sN = v_off[nb + z0];
                eN = v_off[nb + z1 + 1];
            }
            #pragma unroll 1
            for (int j = sC; j < eC; j++) {
                float4 V = sv[j];
                float t2 = fmaf(pz, V.z, fmaf(py, V.y, __fmul_rn(px, V.x)));
                float d = __fsub_rn(V.w, t2);
                int oi = sidx[j];
                if (d < bd || (d == bd && oi < bi)) { bd = d; bi = oi; }
            }
            sC = sN; eC = eN; ix = nix; iy = niy;
        }
        pout[p] = (float)bi;
    }
}

// ---------------- launch ----------------
extern "C" void kernel_launch(void* const* d_in, const int* in_sizes, int n_in,
                              void* d_out, int out_size) {
    const float* xyz = (const float*)d_in[0];
    int n = in_sizes[0] / 3;
    float* out = (float*)d_out;

    int* d_ghist; cudaGetSymbolAddress((void**)&d_ghist, g_hist);
    int* d_goff;  cudaGetSymbolAddress((void**)&d_goff,  g_off);
    int* d_gcur;  cudaGetSymbolAddress((void**)&d_gcur,  g_cur);
    unsigned int* d_mm; cudaGetSymbolAddress((void**)&d_mm, g_mm);

    cudaMemsetAsync(d_ghist, 0, NVOX * sizeof(int));
    cudaMemsetAsync(d_mm, 0xFF, 3 * sizeof(unsigned int));
    cudaMemsetAsync(d_mm + 3, 0x00, 3 * sizeof(unsigned int));

    k_minmax<<<148, 256>>>(xyz, n);
    k_vidhist<<<1024, 256>>>(xyz, n);
    k_scan_a<<<SCANB, 512>>>(d_ghist);
    k_scan_b<<<1, 512>>>(d_goff, n);
    k_scan_c<<<SCANB, 512>>>(d_ghist, d_goff, d_gcur);
    k_scatter<<<1024, 256>>>(xyz, n);
    k_select<<<NVERT, 128>>>(out, n);
    k_vsort<<<1, 1024>>>();

    int smem = NVERT * (int)sizeof(float4) + NVERT * (int)sizeof(unsigned short);
    cudaFuncSetAttribute(k_knn, cudaFuncAttributeMaxDynamicSharedMemorySize, smem);
    k_knn<<<148, 1024, smem>>>(out, n);
}

// round 13
// speedup vs baseline: 2.4729x; 1.4040x over previous
#include <cuda_runtime.h>

#define NVERT 8192
#define GRES 64
#define NVOX (GRES*GRES*GRES)   // 262144
#define NMAX 1048576
#define SCANB 512               // 512 blocks x 512 threads covers NVOX

// ---------------- scratch (device globals; no allocation) ----------------
__device__ unsigned int g_mm[6];        // sortable-uint min(x,y,z), max(x,y,z)
__device__ int g_hist[NVOX];
__device__ int g_off[NVOX + 1];
__device__ int g_cur[NVOX];
__device__ int g_bsum[SCANB];
__device__ int g_bbase[SCANB];
__device__ int g_vid[NMAX];
__device__ float4 g_pts[NMAX];          // voxel-sorted points {x,y,z,bits(origidx)}
__device__ float4 g_vert[NVERT];        // raw {x, y, z, |v|^2}
// vertex grid for pruned knn
__device__ int v_hist[NVOX];
__device__ int v_off[NVOX + 1];
__device__ int v_cur[NVOX];
__device__ int v_cell[NVERT];
__device__ float4 g_vs[NVERT];          // cell-sorted, prescaled {2x,2y,2z,|v|^2}
__device__ unsigned short g_vsidx[NVERT];

// monotone float<->uint mapping (min/max via integer atomics)
__device__ __forceinline__ unsigned f2o(float f) {
    unsigned b = __float_as_uint(f);
    return (b & 0x80000000u) ? ~b : (b | 0x80000000u);
}
__device__ __forceinline__ float o2f(unsigned o) {
    unsigned b = (o & 0x80000000u) ? (o & 0x7FFFFFFFu) : ~o;
    return __uint_as_float(b);
}

// shared helper: per-axis extent guards (must match k_vidhist exactly)
__device__ __forceinline__ void grid_params(float& mnx, float& mny, float& mnz,
                                            float& dx, float& dy, float& dz) {
    mnx = o2f(g_mm[0]); mny = o2f(g_mm[1]); mnz = o2f(g_mm[2]);
    float exx = __fsub_rn(o2f(g_mm[3]), mnx);
    float exy = __fsub_rn(o2f(g_mm[4]), mny);
    float exz = __fsub_rn(o2f(g_mm[5]), mnz);
    dx = exx > 0.f ? exx : 1.f;
    dy = exy > 0.f ? exy : 1.f;
    dz = exz > 0.f ? exz : 1.f;
}

// ---------------- 2. global min/max per coordinate ----------------
__global__ void k_minmax(const float* __restrict__ xyz, int n) {
    float mnx = 3.402823466e38f, mny = mnx, mnz = mnx;
    float mxx = -3.402823466e38f, mxy = mxx, mxz = mxx;
    for (int i = blockIdx.x * blockDim.x + threadIdx.x; i < n;
         i += gridDim.x * blockDim.x) {
        float x = xyz[3 * i], y = xyz[3 * i + 1], z = xyz[3 * i + 2];
        mnx = fminf(mnx, x); mny = fminf(mny, y); mnz = fminf(mnz, z);
        mxx = fmaxf(mxx, x); mxy = fmaxf(mxy, y); mxz = fmaxf(mxz, z);
    }
    for (int o = 16; o; o >>= 1) {
        mnx = fminf(mnx, __shfl_xor_sync(0xFFFFFFFFu, mnx, o));
        mny = fminf(mny, __shfl_xor_sync(0xFFFFFFFFu, mny, o));
        mnz = fminf(mnz, __shfl_xor_sync(0xFFFFFFFFu, mnz, o));
        mxx = fmaxf(mxx, __shfl_xor_sync(0xFFFFFFFFu, mxx, o));
        mxy = fmaxf(mxy, __shfl_xor_sync(0xFFFFFFFFu, mxy, o));
        mxz = fmaxf(mxz, __shfl_xor_sync(0xFFFFFFFFu, mxz, o));
    }
    if ((threadIdx.x & 31) == 0) {
        atomicMin(&g_mm[0], f2o(mnx));
        atomicMin(&g_mm[1], f2o(mny));
        atomicMin(&g_mm[2], f2o(mnz));
        atomicMax(&g_mm[3], f2o(mxx));
        atomicMax(&g_mm[4], f2o(mxy));
        atomicMax(&g_mm[5], f2o(mxz));
    }
}

// ---------------- 3. voxel id + histogram (reciprocal-hoisted division) ----
__global__ void k_vidhist(const float* __restrict__ xyz, int n) {
    float mnx, mny, mnz, dx, dy, dz;
    grid_params(mnx, mny, mnz, dx, dy, dz);
    float rx = __fdiv_rn(1.0f, dx);
    float ry = __fdiv_rn(1.0f, dy);
    float rz = __fdiv_rn(1.0f, dz);
    const float HI = (float)(1.0 - 1e-6);
    for (int i = blockIdx.x * blockDim.x + threadIdx.x; i < n;
         i += gridDim.x * blockDim.x) {
        float ux = __fmul_rn(__fsub_rn(xyz[3 * i],     mnx), rx);
        float uy = __fmul_rn(__fsub_rn(xyz[3 * i + 1], mny), ry);
        float uz = __fmul_rn(__fsub_rn(xyz[3 * i + 2], mnz), rz);
        ux = fminf(fmaxf(ux, 0.f), HI);
        uy = fminf(fmaxf(uy, 0.f), HI);
        uz = fminf(fmaxf(uz, 0.f), HI);
        int vx = (int)floorf(__fmul_rn(ux, (float)GRES));
        int vy = (int)floorf(__fmul_rn(uy, (float)GRES));
        int vz = (int)floorf(__fmul_rn(uz, (float)GRES));
        int vid = (vx * GRES + vy) * GRES + vz;
        g_vid[i] = vid;
        atomicAdd(&g_hist[vid], 1);
    }
}

// ---------------- 4. generic exclusive scan over NVOX (3 kernels) ----------
__global__ void k_scan_a(const int* __restrict__ hist) {
    __shared__ int sh[512];
    int i = blockIdx.x * 512 + threadIdx.x;
    sh[threadIdx.x] = hist[i];
    __syncthreads();
    for (int off = 256; off; off >>= 1) {
        if (threadIdx.x < off) sh[threadIdx.x] += sh[threadIdx.x + off];
        __syncthreads();
    }
    if (threadIdx.x == 0) g_bsum[blockIdx.x] = sh[0];
}
__global__ void k_scan_b(int* __restrict__ off, int total) {
    __shared__ int sh[512];
    int v = g_bsum[threadIdx.x];
    sh[threadIdx.x] = v;
    __syncthreads();
    for (int o = 1; o < 512; o <<= 1) {
        int t = (threadIdx.x >= o) ? sh[threadIdx.x - o] : 0;
        __syncthreads();
        sh[threadIdx.x] += t;
        __syncthreads();
    }
    g_bbase[threadIdx.x] = sh[threadIdx.x] - v;
    if (threadIdx.x == 0) off[NVOX] = total;
}
__global__ void k_scan_c(const int* __restrict__ hist, int* __restrict__ off,
                         int* __restrict__ cur) {
    __shared__ int sh[512];
    int i = blockIdx.x * 512 + threadIdx.x;
    int v = hist[i];
    sh[threadIdx.x] = v;
    __syncthreads();
    for (int o = 1; o < 512; o <<= 1) {
        int t = (threadIdx.x >= o) ? sh[threadIdx.x - o] : 0;
        __syncthreads();
        sh[threadIdx.x] += t;
        __syncthreads();
    }
    int excl = sh[threadIdx.x] - v + g_bbase[blockIdx.x];
    off[i] = excl;
    cur[i] = excl;
}

// ---------------- 5. counting-sort scatter: packed point records -----------
__global__ void k_scatter(const float* __restrict__ xyz, int n) {
    for (int i = blockIdx.x * blockDim.x + threadIdx.x; i < n;
         i += gridDim.x * blockDim.x) {
        int v = g_vid[i];
        int pos = atomicAdd(&g_cur[v], 1);
        g_pts[pos] = make_float4(xyz[3 * i], xyz[3 * i + 1], xyz[3 * i + 2],
                                 __int_as_float(i));
    }
}

// ---------------- 6. stable selection of 8192 vertices (+ vertex binning) --
// sel per f32 jnp.linspace: delta = RN((n-1)/8191); s = floor(RN(q*delta)).
__global__ void k_select(float* __restrict__ out, int n) {
    __shared__ int sb[4096];
    __shared__ int info[3];
    int q = blockIdx.x;
    if (threadIdx.x == 0) {
        float delta = __fdiv_rn((float)(n - 1), (float)(NVERT - 1));
        float fv = __fmul_rn((float)q, delta);
        int s = (int)floorf(fv);
        int lo = 0, hi = NVOX;
        while (hi - lo > 1) {
            int mid = (lo + hi) >> 1;
            if (g_off[mid] <= s) lo = mid; else hi = mid;
        }
        info[0] = g_off[lo];
        info[1] = g_off[lo + 1] - g_off[lo];
        info[2] = s - g_off[lo];
    }
    __syncthreads();
    int base = info[0], m = info[1], r = info[2];

    float mnx, mny, mnz, dx, dy, dz;
    grid_params(mnx, mny, mnz, dx, dy, dz);
    float ivx = __fdiv_rn((float)GRES, dx);
    float ivy = __fdiv_rn((float)GRES, dy);
    float ivz = __fdiv_rn((float)GRES, dz);

    if (m <= 4096) {
        for (int j = threadIdx.x; j < m; j += blockDim.x)
            sb[j] = __float_as_int(g_pts[base + j].w);
        __syncthreads();
        for (int j = threadIdx.x; j < m; j += blockDim.x) {
            int x = sb[j], c = 0;
            for (int t = 0; t < m; t++) c += (sb[t] < x);
            if (c == r) {
                float4 P = g_pts[base + j];
                out[3 * q] = P.x; out[3 * q + 1] = P.y; out[3 * q + 2] = P.z;
                float vn = __fadd_rn(__fadd_rn(__fmul_rn(P.x, P.x), __fmul_rn(P.y, P.y)),
                                     __fmul_rn(P.z, P.z));
                g_vert[q] = make_float4(P.x, P.y, P.z, vn);
                int cx = min(max((int)floorf((P.x - mnx) * ivx), 0), GRES - 1);
                int cy = min(max((int)floorf((P.y - mny) * ivy), 0), GRES - 1);
                int cz = min(max((int)floorf((P.z - mnz) * ivz), 0), GRES - 1);
                int cell = (cx * GRES + cy) * GRES + cz;
                v_cell[q] = cell;
                atomicAdd(&v_hist[cell], 1);
            }
        }
    } else {
        for (int j = threadIdx.x; j < m; j += blockDim.x) {
            int x = __float_as_int(g_pts[base + j].w), c = 0;
            for (int t = 0; t < m; t++)
                c += (__float_as_int(g_pts[base + t].w) < x);
            if (c == r) {
                float4 P = g_pts[base + j];
                out[3 * q] = P.x; out[3 * q + 1] = P.y; out[3 * q + 2] = P.z;
                float vn = __fadd_rn(__fadd_rn(__fmul_rn(P.x, P.x), __fmul_rn(P.y, P.y)),
                                     __fmul_rn(P.z, P.z));
                g_vert[q] = make_float4(P.x, P.y, P.z, vn);
                int cx = min(max((int)floorf((P.x - mnx) * ivx), 0), GRES - 1);
                int cy = min(max((int)floorf((P.y - mny) * ivy), 0), GRES - 1);
                int cz = min(max((int)floorf((P.z - mnz) * ivz), 0), GRES - 1);
                int cell = (cx * GRES + cy) * GRES + cz;
                v_cell[q] = cell;
                atomicAdd(&v_hist[cell], 1);
            }
        }
    }
}

// ---------------- 6c. scatter vertices (prescaled by 2) --------------------
__global__ void k_vscatter() {
    int q = blockIdx.x * blockDim.x + threadIdx.x;
    if (q >= NVERT) return;
    int c = v_cell[q];
    int pos = atomicAdd(&v_cur[c], 1);
    float4 v = g_vert[q];
    g_vs[pos] = make_float4(2.0f * v.x, 2.0f * v.y, 2.0f * v.z, v.w);
    g_vsidx[pos] = (unsigned short)q;
}

// ---------------- 7. grid-pruned 1-NN (R9 champion + tighter margin) -------
// Phase A: octant 2^3 box, all 8 v_off LDGs issued up-front (MLP=8).
// Phase B: exact reference-formula rescan of sphere box, margin
// sqrt(D+1e-4)+1e-4 (still ~100x worst-case float drift of ~1e-6);
// flattened rows with 1-ahead (s,e) prefetch.
__global__ void __launch_bounds__(1024, 1)
k_knn(float* __restrict__ out, int n) {
    extern __shared__ char smem[];
    float4* sv = (float4*)smem;                         // 8192 * 16B
    unsigned short* sidx = (unsigned short*)(smem + NVERT * sizeof(float4));
    for (int j = threadIdx.x; j < NVERT; j += blockDim.x) {
        sv[j] = g_vs[j];
        sidx[j] = g_vsidx[j];
    }
    __syncthreads();

    float mnx, mny, mnz, dx, dy, dz;
    grid_params(mnx, mny, mnz, dx, dy, dz);
    float ivx = __fdiv_rn((float)GRES, dx);
    float ivy = __fdiv_rn((float)GRES, dy);
    float ivz = __fdiv_rn((float)GRES, dz);
    float* pout = out + 3 * NVERT;

    for (int i = blockIdx.x * blockDim.x + threadIdx.x; i < n;
         i += gridDim.x * blockDim.x) {
        float4 P = g_pts[i];                // coalesced
        float px = P.x, py = P.y, pz = P.z;
        int p = __float_as_int(P.w);
        float fx = (px - mnx) * ivx, fy = (py - mny) * ivy, fz = (pz - mnz) * ivz;
        int cx = min(max((int)floorf(fx), 0), GRES - 1);
        int cy = min(max((int)floorf(fy), 0), GRES - 1);
        int cz = min(max((int)floorf(fz), 0), GRES - 1);

        // ---- phase A: octant 2^3 box, bounds prefetched with MLP=8 ----
        float bestD = 3.402823466e38f;
        {
            int x0 = (fx - (float)cx > 0.5f) ? cx : cx - 1;
            int y0 = (fy - (float)cy > 0.5f) ? cy : cy - 1;
            int z0 = (fz - (float)cz > 0.5f) ? cz : cz - 1;
            x0 = max(x0, 0); int x1 = min(x0 + 1, GRES - 1); x0 = min(x0, x1);
            y0 = max(y0, 0); int y1 = min(y0 + 1, GRES - 1); y0 = min(y0, y1);
            z0 = max(z0, 0); int z1 = min(z0 + 1, GRES - 1); z0 = min(z0, z1);
            int r00 = (x0 * GRES + y0) * GRES;
            int r01 = (x0 * GRES + y1) * GRES;
            int r10 = (x1 * GRES + y0) * GRES;
            int r11 = (x1 * GRES + y1) * GRES;
            int s00 = v_off[r00 + z0], e00 = v_off[r00 + z1 + 1];
            int s01 = v_off[r01 + z0], e01 = v_off[r01 + z1 + 1];
            int s10 = v_off[r10 + z0], e10 = v_off[r10 + z1 + 1];
            int s11 = v_off[r11 + z0], e11 = v_off[r11 + z1 + 1];
            #pragma unroll 1
            for (int j = s00; j < e00; j++) {
                float4 V = sv[j];
                float ddx = px - 0.5f * V.x, ddy = py - 0.5f * V.y, ddz = pz - 0.5f * V.z;
                bestD = fminf(bestD, fmaf(ddz, ddz, fmaf(ddy, ddy, ddx * ddx)));
            }
            #pragma unroll 1
            for (int j = s01; j < e01; j++) {
                float4 V = sv[j];
                float ddx = px - 0.5f * V.x, ddy = py - 0.5f * V.y, ddz = pz - 0.5f * V.z;
                bestD = fminf(bestD, fmaf(ddz, ddz, fmaf(ddy, ddy, ddx * ddx)));
            }
            #pragma unroll 1
            for (int j = s10; j < e10; j++) {
                float4 V = sv[j];
                float ddx = px - 0.5f * V.x, ddy = py - 0.5f * V.y, ddz = pz - 0.5f * V.z;
                bestD = fminf(bestD, fmaf(ddz, ddz, fmaf(ddy, ddy, ddx * ddx)));
            }
            #pragma unroll 1
            for (int j = s11; j < e11; j++) {
                float4 V = sv[j];
                float ddx = px - 0.5f * V.x, ddy = py - 0.5f * V.y, ddz = pz - 0.5f * V.z;
                bestD = fminf(bestD, fmaf(ddz, ddz, fmaf(ddy, ddy, ddx * ddx)));
            }
        }
        // fallback: expanding boxes until any vertex found (rare)
        if (bestD >= 3.0e38f) {
            for (int w = 1; w < GRES; w++) {
                int x0 = max(cx - w, 0), x1 = min(cx + w, GRES - 1);
                int y0 = max(cy - w, 0), y1 = min(cy + w, GRES - 1);
                int z0 = max(cz - w, 0), z1 = min(cz + w, GRES - 1);
                for (int ix = x0; ix <= x1; ix++)
                    for (int iy = y0; iy <= y1; iy++) {
                        int row = (ix * GRES + iy) * GRES;
                        int s = v_off[row + z0];
                        int e = v_off[row + z1 + 1];
                        for (int j = s; j < e; j++) {
                            float4 V = sv[j];
                            float ddx = px - 0.5f * V.x, ddy = py - 0.5f * V.y, ddz = pz - 0.5f * V.z;
                            bestD = fminf(bestD, fmaf(ddz, ddz, fmaf(ddy, ddy, ddx * ddx)));
                        }
                    }
                if (bestD < 3.0e38f) break;
            }
        }

        // ---- phase B: exact rescan of sphere box, 1-ahead row prefetch ----
        float R = sqrtf(bestD + 1e-4f) + 1e-4f;
        int x0 = min(max((int)floorf((px - R - mnx) * ivx), 0), GRES - 1);
        int x1 = min(max((int)floorf((px + R - mnx) * ivx), 0), GRES - 1);
        int y0 = min(max((int)floorf((py - R - mny) * ivy), 0), GRES - 1);
        int y1 = min(max((int)floorf((py + R - mny) * ivy), 0), GRES - 1);
        int z0 = min(max((int)floorf((pz - R - mnz) * ivz), 0), GRES - 1);
        int z1 = min(max((int)floorf((pz + R - mnz) * ivz), 0), GRES - 1);

        float bd = 3.402823466e38f;
        int bi = 0x7FFFFFFF;
        int ny = y1 - y0 + 1;
        int nr = (x1 - x0 + 1) * ny;
        int ix = x0, iy = y0;
        int rowb = (ix * GRES + iy) * GRES;
        int sC = v_off[rowb + z0], eC = v_off[rowb + z1 + 1];
        for (int r = 0; r < nr; r++) {
            int nix = ix, niy = iy + 1;
            if (niy > y1) { niy = y0; nix = ix + 1; }
            int sN = 0, eN = 0;
            if (r + 1 < nr) {
                int nb = (nix * GRES + niy) * GRES;
                sN = v_off[nb + z0];
                eN = v_off[nb + z1 + 1];
            }
            #pragma unroll 1
            for (int j = sC; j < eC; j++) {
                float4 V = sv[j];
                float t2 = fmaf(pz, V.z, fmaf(py, V.y, __fmul_rn(px, V.x)));
                float d = __fsub_rn(V.w, t2);
                int oi = sidx[j];
                if (d < bd || (d == bd && oi < bi)) { bd = d; bi = oi; }
            }
            sC = sN; eC = eN; ix = nix; iy = niy;
        }
        pout[p] = (float)bi;
    }
}

// ---------------- launch ----------------
extern "C" void kernel_launch(void* const* d_in, const int* in_sizes, int n_in,
                              void* d_out, int out_size) {
    const float* xyz = (const float*)d_in[0];
    int n = in_sizes[0] / 3;
    float* out = (float*)d_out;

    int* d_ghist; cudaGetSymbolAddress((void**)&d_ghist, g_hist);
    int* d_goff;  cudaGetSymbolAddress((void**)&d_goff,  g_off);
    int* d_gcur;  cudaGetSymbolAddress((void**)&d_gcur,  g_cur);
    int* d_vhist; cudaGetSymbolAddress((void**)&d_vhist, v_hist);
    int* d_voff;  cudaGetSymbolAddress((void**)&d_voff,  v_off);
    int* d_vcur;  cudaGetSymbolAddress((void**)&d_vcur,  v_cur);
    unsigned int* d_mm; cudaGetSymbolAddress((void**)&d_mm, g_mm);

    // init via memset nodes
    cudaMemsetAsync(d_ghist, 0, NVOX * sizeof(int));
    cudaMemsetAsync(d_vhist, 0, NVOX * sizeof(int));
    cudaMemsetAsync(d_mm, 0xFF, 3 * sizeof(unsigned int));
    cudaMemsetAsync(d_mm + 3, 0x00, 3 * sizeof(unsigned int));

    k_minmax<<<148, 256>>>(xyz, n);
    k_vidhist<<<1024, 256>>>(xyz, n);
    k_scan_a<<<SCANB, 512>>>(d_ghist);
    k_scan_b<<<1, 512>>>(d_goff, n);
    k_scan_c<<<SCANB, 512>>>(d_ghist, d_goff, d_gcur);
    k_scatter<<<1024, 256>>>(xyz, n);
    k_select<<<NVERT, 128>>>(out, n);
    k_scan_a<<<SCANB, 512>>>(d_vhist);
    k_scan_b<<<1, 512>>>(d_voff, NVERT);
    k_scan_c<<<SCANB, 512>>>(d_vhist, d_voff, d_vcur);
    k_vscatter<<<16, 512>>>();

    int smem = NVERT * (int)sizeof(float4) + NVERT * (int)sizeof(unsigned short);
    cudaFuncSetAttribute(k_knn, cudaFuncAttributeMaxDynamicSharedMemorySize, smem);
    k_knn<<<148, 1024, smem>>>(out, n);
}